// round 5
// baseline (speedup 1.0000x reference)
#include <cuda_runtime.h>
#include <cuda_bf16.h>
#include <cstdint>

// Problem constants
#define M_TOT 16384          // B*T
#define NDIM  512
#define NBH   32             // B*H
#define TSPLIT 32

// ---------------- scratch (__device__ globals; no allocation allowed) -------
__device__ float g_q[M_TOT * NDIM];
__device__ float g_k[M_TOT * NDIM];
__device__ float g_v[M_TOT * NDIM];
__device__ float g_ctx[NBH * 64 * 64];
__device__ float g_ksum[NBH * 64];
__device__ float g_ctxp[TSPLIT * NBH * 64 * 64];
__device__ float g_ksump[TSPLIT * NBH * 64];
__device__ __nv_bfloat16 g_xh[M_TOT * NDIM];
__device__ __nv_bfloat16 g_xl[M_TOT * NDIM];
__device__ __nv_bfloat16 g_oh[M_TOT * NDIM];
__device__ __nv_bfloat16 g_ol[M_TOT * NDIM];
__device__ __nv_bfloat16 g_wh[4 * NDIM * NDIM];
__device__ __nv_bfloat16 g_wl[4 * NDIM * NDIM];

// ---------------- helpers ---------------------------------------------------
__device__ __forceinline__ uint32_t smem_u32(const void* p) {
    uint32_t a;
    asm("{ .reg .u64 t; cvta.to.shared.u64 t, %1; cvt.u32.u64 %0, t; }" : "=r"(a) : "l"(p));
    return a;
}
#define SWZ(o) ((o) ^ (((o) >> 3) & 0x70))

__device__ __forceinline__ void cp16(uint32_t dst, const void* src) {
    asm volatile("cp.async.cg.shared.global [%0], [%1], 16;" :: "r"(dst), "l"(src));
}
#define CP_COMMIT() asm volatile("cp.async.commit_group;" ::: "memory")
#define CP_WAIT(n)  asm volatile("cp.async.wait_group %0;" :: "n"(n) : "memory")

#define LDSM4(r, addr) \
    asm volatile("ldmatrix.sync.aligned.m8n8.x4.shared.b16 {%0,%1,%2,%3}, [%4];" \
        : "=r"((r)[0]), "=r"((r)[1]), "=r"((r)[2]), "=r"((r)[3]) : "r"(addr))

#define MMA_BF16(d, a, b0, b1) \
    asm volatile("mma.sync.aligned.m16n8k16.row.col.f32.bf16.bf16.f32 " \
        "{%0,%1,%2,%3}, {%4,%5,%6,%7}, {%8,%9}, {%0,%1,%2,%3};" \
        : "+f"((d)[0]), "+f"((d)[1]), "+f"((d)[2]), "+f"((d)[3]) \
        : "r"((a)[0]), "r"((a)[1]), "r"((a)[2]), "r"((a)[3]), "r"(b0), "r"(b1))

// ---------------------------------------------------------------------------
// HMMA GEMM v2, hi/lo bf16 split with shared operand tiles:
// per K=64 step load {Ah, Al, Bh, Bl} once (64KB stage), run 3 MMA terms
// (AhBh + AlBh + AhBl) from smem. Tile BM=128, BN=128; 8 warps (4m x 2n),
// warp tile 32x64; 3-stage cp.async pipeline; fused per-head softmax epilogue.
// ---------------------------------------------------------------------------
#define BKB   128            // bytes per smem row (64 bf16)
#define K0B   16384          // one 128x64 bf16 tile
#define STG   (4 * K0B)      // 64KB stage: Ah | Al | Bh | Bl
#define NSTG  3
#define SMEM_GEMM (NSTG * STG)
#define K0STEPS 8

struct GArgs {
    const __nv_bfloat16 *Ah, *Al, *Wh, *Wl;   // Wh/Wl: base of (multi-)slice weights
    const float *b0, *b1, *b2;                // bias per 512-col slice
    float *o0, *o1, *o2;                      // output per 512-col slice
};

__device__ __forceinline__ void load_k0(
    uint32_t sbase, int stage, int k0, int bm, int bnn, int tid,
    const __nv_bfloat16* Ah, const __nv_bfloat16* Al,
    const __nv_bfloat16* Bh, const __nv_bfloat16* Bl)
{
    uint32_t s = sbase + stage * STG;
#pragma unroll
    for (int t = 0; t < 4; t++) {
        int idx = tid + t * 256;                  // 1024 x 16B per tile
        int row = idx >> 3, c = idx & 7;
        uint32_t off = SWZ((uint32_t)(row * BKB + c * 16));
        size_t ga = (size_t)(bm + row) * 512 + k0 + c * 8;
        size_t gb = (size_t)(bnn + row) * 512 + k0 + c * 8;
        cp16(s + off,            Ah + ga);
        cp16(s + K0B + off,      Al + ga);
        cp16(s + 2 * K0B + off,  Bh + gb);
        cp16(s + 3 * K0B + off,  Bl + gb);
    }
}

template <bool FUSED>
__global__ __launch_bounds__(256, 1) void mma_gemm_k(GArgs args)
{
    extern __shared__ char smem[];
    uint32_t sbase = smem_u32(smem);

    const int tid = threadIdx.x;
    const int wid = tid >> 5;
    const int lane = tid & 31;
    const int wm = (wid & 3) * 32;       // warp m offset
    const int wn = (wid >> 2) * 64;      // warp n offset
    const int bm = blockIdx.y * 128;
    const int bn = blockIdx.x * 128;
    const int slice = bn >> 9;           // which 512-col slice (0..2)
    const int bnn = bn & 511;            // col offset within slice

    const __nv_bfloat16* Bh = args.Wh + (size_t)slice * NDIM * NDIM;
    const __nv_bfloat16* Bl = args.Wl + (size_t)slice * NDIM * NDIM;
    const float* bias = (slice == 0) ? args.b0 : (slice == 1) ? args.b1 : args.b2;
    float* Cout       = (slice == 0) ? args.o0 : (slice == 1) ? args.o1 : args.o2;
    const bool do_sm = FUSED && (slice < 2);

    float acc[2][8][4];
#pragma unroll
    for (int i = 0; i < 2; i++)
#pragma unroll
        for (int j = 0; j < 8; j++)
#pragma unroll
            for (int p = 0; p < 4; p++) acc[i][j][p] = 0.f;

    const int a_row = wm + (lane & 15);
    const int a_cb  = (lane >> 4) * 16;
    const int b_row = wn + (lane & 7) + ((lane >> 4) & 1) * 8;
    const int b_cb  = ((lane >> 3) & 1) * 16;

    load_k0(sbase, 0, 0, bm, bnn, tid, args.Ah, args.Al, Bh, Bl);
    CP_COMMIT();
    load_k0(sbase, 1, 64, bm, bnn, tid, args.Ah, args.Al, Bh, Bl);
    CP_COMMIT();

    for (int i = 0; i < K0STEPS; i++) {
        CP_WAIT(1);
        __syncthreads();
        if (i + 2 < K0STEPS)
            load_k0(sbase, (i + 2) % NSTG, (i + 2) * 64, bm, bnn, tid,
                    args.Ah, args.Al, Bh, Bl);
        CP_COMMIT();

        uint32_t sAh = sbase + (i % NSTG) * STG;
        uint32_t sAl = sAh + K0B;
        uint32_t sBh = sAh + 2 * K0B;
        uint32_t sBl = sAh + 3 * K0B;
#pragma unroll
        for (int ks = 0; ks < 4; ks++) {
            uint32_t ah[2][4], al[2][4], bh[4][4], bl[4][4];
#pragma unroll
            for (int mi = 0; mi < 2; mi++) {
                uint32_t off = SWZ((uint32_t)((a_row + mi * 16) * BKB + ks * 32 + a_cb));
                LDSM4(ah[mi], sAh + off);
                LDSM4(al[mi], sAl + off);
            }
#pragma unroll
            for (int nb = 0; nb < 4; nb++) {
                uint32_t off = SWZ((uint32_t)((b_row + nb * 16) * BKB + ks * 32 + b_cb));
                LDSM4(bh[nb], sBh + off);
                LDSM4(bl[nb], sBl + off);
            }
#pragma unroll
            for (int mi = 0; mi < 2; mi++)
#pragma unroll
                for (int nb = 0; nb < 4; nb++) {
                    MMA_BF16(acc[mi][nb * 2 + 0], ah[mi], bh[nb][0], bh[nb][1]);
                    MMA_BF16(acc[mi][nb * 2 + 1], ah[mi], bh[nb][2], bh[nb][3]);
                    MMA_BF16(acc[mi][nb * 2 + 0], al[mi], bh[nb][0], bh[nb][1]);
                    MMA_BF16(acc[mi][nb * 2 + 1], al[mi], bh[nb][2], bh[nb][3]);
                    MMA_BF16(acc[mi][nb * 2 + 0], ah[mi], bl[nb][0], bl[nb][1]);
                    MMA_BF16(acc[mi][nb * 2 + 1], ah[mi], bl[nb][2], bl[nb][3]);
                }
        }
    }

    // ---- epilogue: bias, optional per-head softmax, store -----------------
#pragma unroll
    for (int nf = 0; nf < 8; nf++) {
        int col = bnn + wn + (lane & 3) * 2 + nf * 8;
        float bb0 = __ldg(bias + col);
        float bb1 = __ldg(bias + col + 1);
#pragma unroll
        for (int mi = 0; mi < 2; mi++) {
            acc[mi][nf][0] += bb0; acc[mi][nf][1] += bb1;
            acc[mi][nf][2] += bb0; acc[mi][nf][3] += bb1;
        }
    }

    if (do_sm) {
        // softmax over the warp's 64 cols, per row (row = lane quad).
#pragma unroll
        for (int mi = 0; mi < 2; mi++)
#pragma unroll
            for (int half = 0; half < 2; half++) {
                float m = -1e30f;
#pragma unroll
                for (int nf = 0; nf < 8; nf++)
                    m = fmaxf(m, fmaxf(acc[mi][nf][half * 2], acc[mi][nf][half * 2 + 1]));
                m = fmaxf(m, __shfl_xor_sync(0xffffffffu, m, 1));
                m = fmaxf(m, __shfl_xor_sync(0xffffffffu, m, 2));
                float s = 0.f;
#pragma unroll
                for (int nf = 0; nf < 8; nf++) {
                    float e0 = __expf(acc[mi][nf][half * 2] - m);
                    float e1 = __expf(acc[mi][nf][half * 2 + 1] - m);
                    acc[mi][nf][half * 2] = e0;
                    acc[mi][nf][half * 2 + 1] = e1;
                    s += e0 + e1;
                }
                s += __shfl_xor_sync(0xffffffffu, s, 1);
                s += __shfl_xor_sync(0xffffffffu, s, 2);
                float inv = 1.f / s;
#pragma unroll
                for (int nf = 0; nf < 8; nf++) {
                    acc[mi][nf][half * 2] *= inv;
                    acc[mi][nf][half * 2 + 1] *= inv;
                }
            }
    }

    const int r0 = bm + wm + (lane >> 2);
    const int c0 = bnn + wn + (lane & 3) * 2;
#pragma unroll
    for (int nf = 0; nf < 8; nf++) {
        int col = c0 + nf * 8;
#pragma unroll
        for (int mi = 0; mi < 2; mi++) {
            int row = r0 + mi * 16;
            float2 v0 = {acc[mi][nf][0], acc[mi][nf][1]};
            float2 v1 = {acc[mi][nf][2], acc[mi][nf][3]};
            *(float2*)(Cout + (size_t)row * 512 + col) = v0;
            *(float2*)(Cout + (size_t)(row + 8) * 512 + col) = v1;
        }
    }
}

// ---------------------------------------------------------------------------
// fused hi/lo split: x and all four weight matrices in one launch
// ---------------------------------------------------------------------------
#define NX  (M_TOT * NDIM)          // 8388608
#define NW1 (NDIM * NDIM)           // 262144

__device__ __forceinline__ void split4(const float* s, __nv_bfloat16* h,
                                       __nv_bfloat16* l, int i)
{
    float4 v = *(const float4*)(s + i);
    __nv_bfloat16 h0 = __float2bfloat16(v.x), h1 = __float2bfloat16(v.y);
    __nv_bfloat16 h2 = __float2bfloat16(v.z), h3 = __float2bfloat16(v.w);
    __nv_bfloat162 hh0{h0, h1}, hh1{h2, h3};
    __nv_bfloat162 ll0{__float2bfloat16(v.x - __bfloat162float(h0)),
                       __float2bfloat16(v.y - __bfloat162float(h1))};
    __nv_bfloat162 ll1{__float2bfloat16(v.z - __bfloat162float(h2)),
                       __float2bfloat16(v.w - __bfloat162float(h3))};
    // h/l already offset to region base
    *(__nv_bfloat162*)(h + i) = hh0; *(__nv_bfloat162*)(h + i + 2) = hh1;
    *(__nv_bfloat162*)(l + i) = ll0; *(__nv_bfloat162*)(l + i + 2) = ll1;
}

__global__ __launch_bounds__(256) void split_all_k(
    const float* __restrict__ x,
    const float* __restrict__ Wq, const float* __restrict__ Wk,
    const float* __restrict__ Wv, const float* __restrict__ Wp,
    __nv_bfloat16* __restrict__ xh, __nv_bfloat16* __restrict__ xl,
    __nv_bfloat16* __restrict__ wh, __nv_bfloat16* __restrict__ wl)
{
    int i = (blockIdx.x * 256 + threadIdx.x) * 4;
    if (i < NX) {
        split4(x, xh, xl, i);
    } else {
        int j = i - NX;                  // 0 .. 4*NW1-1
        int w = j >> 18;                 // NW1 = 2^18
        int o = j & (NW1 - 1);
        const float* src = (w == 0) ? Wq : (w == 1) ? Wk : (w == 2) ? Wv : Wp;
        float4 v = *(const float4*)(src + o);
        __nv_bfloat16 h0 = __float2bfloat16(v.x), h1 = __float2bfloat16(v.y);
        __nv_bfloat16 h2 = __float2bfloat16(v.z), h3 = __float2bfloat16(v.w);
        __nv_bfloat162 hh0{h0, h1}, hh1{h2, h3};
        __nv_bfloat162 ll0{__float2bfloat16(v.x - __bfloat162float(h0)),
                           __float2bfloat16(v.y - __bfloat162float(h1))};
        __nv_bfloat162 ll1{__float2bfloat16(v.z - __bfloat162float(h2)),
                           __float2bfloat16(v.w - __bfloat162float(h3))};
        *(__nv_bfloat162*)(wh + j) = hh0; *(__nv_bfloat162*)(wh + j + 2) = hh1;
        *(__nv_bfloat162*)(wl + j) = ll0; *(__nv_bfloat162*)(wl + j + 2) = ll1;
    }
}

// ---------------------------------------------------------------------------
// context partials + k_sum partials (fp32); T slice of 128 per block
// ---------------------------------------------------------------------------
__global__ __launch_bounds__(256) void ctx_partial_k(
    const float* __restrict__ K, const float* __restrict__ V,
    float* __restrict__ ctxp, float* __restrict__ ksump)
{
    __shared__ float ks[32][65];
    __shared__ float vs[32][65];
    const int bh = blockIdx.x, b = bh >> 3, h = bh & 7;
    const int ts = blockIdx.y, tid = threadIdx.x;
    const int tx = tid & 15, ty = tid >> 4;
    const int col = tid & 63, trow = tid >> 6;

    float acc[4][4];
#pragma unroll
    for (int i = 0; i < 4; i++)
#pragma unroll
        for (int j = 0; j < 4; j++) acc[i][j] = 0.f;
    float ksacc[4] = {0.f, 0.f, 0.f, 0.f};
    const int rowbase = b * 4096 + ts * 128;

    for (int tt = 0; tt < 128; tt += 32) {
#pragma unroll
        for (int p = 0; p < 8; p++) {
            int t = trow + p * 4;
            size_t g = (size_t)(rowbase + tt + t) * 512 + h * 64 + col;
            ks[t][col] = K[g]; vs[t][col] = V[g];
        }
        __syncthreads();
#pragma unroll
        for (int t = 0; t < 32; t++) {
            float a[4], bb[4];
#pragma unroll
            for (int i = 0; i < 4; i++) a[i] = ks[t][ty * 4 + i];
#pragma unroll
            for (int j = 0; j < 4; j++) bb[j] = vs[t][tx * 4 + j];
#pragma unroll
            for (int i = 0; i < 4; i++)
#pragma unroll
                for (int j = 0; j < 4; j++) acc[i][j] += a[i] * bb[j];
            if (tx == 0)
#pragma unroll
                for (int i = 0; i < 4; i++) ksacc[i] += a[i];
        }
        __syncthreads();
    }
    float* cp = ctxp + (size_t)(ts * NBH + bh) * 4096;
#pragma unroll
    for (int i = 0; i < 4; i++)
#pragma unroll
        for (int j = 0; j < 4; j++)
            cp[(ty * 4 + i) * 64 + tx * 4 + j] = acc[i][j];
    if (tx == 0)
#pragma unroll
        for (int i = 0; i < 4; i++)
            ksump[(size_t)(ts * NBH + bh) * 64 + ty * 4 + i] = ksacc[i];
}

// combined reduce: ctx (NBH*4096) then ksum (NBH*64)
__global__ void reduce_all_k(const float* __restrict__ ctxp,
                             const float* __restrict__ ksump,
                             float* __restrict__ ctx, float* __restrict__ ksum)
{
    int i = blockIdx.x * blockDim.x + threadIdx.x;
    if (i < NBH * 4096) {
        float s = 0.f;
#pragma unroll
        for (int p = 0; p < TSPLIT; p++) s += ctxp[(size_t)p * NBH * 4096 + i];
        ctx[i] = s;
    } else {
        int j = i - NBH * 4096;
        if (j < NBH * 64) {
            float s = 0.f;
#pragma unroll
            for (int p = 0; p < TSPLIT; p++) s += ksump[(size_t)p * NBH * 64 + j];
            ksum[j] = s;
        }
    }
}

// ---------------------------------------------------------------------------
// out = (q @ ctx) * Dinv + q  -> written as bf16 hi/lo for final GEMM
// ---------------------------------------------------------------------------
__global__ __launch_bounds__(256) void attn_out_k(
    const float* __restrict__ Q, const float* __restrict__ ctx,
    const float* __restrict__ ksum,
    __nv_bfloat16* __restrict__ Oh, __nv_bfloat16* __restrict__ Ol)
{
    __shared__ float cs[64][64];
    __shared__ float qs[64][65];
    __shared__ float kss[64];
    const int bh = blockIdx.x, b = bh >> 3, h = bh & 7;
    const int tb = blockIdx.y, tid = threadIdx.x;

    const float* cg = ctx + (size_t)bh * 4096;
    for (int i = tid; i < 4096; i += 256) cs[i >> 6][i & 63] = cg[i];
    if (tid < 64) kss[tid] = ksum[bh * 64 + tid];

    const int rowbase = b * 4096 + tb * 64;
    const int col = tid & 63, rr = tid >> 6;
#pragma unroll
    for (int p = 0; p < 16; p++) {
        int r = rr + p * 4;
        qs[r][col] = Q[(size_t)(rowbase + r) * 512 + h * 64 + col];
    }
    __syncthreads();

    const int r = tid >> 2, e0 = (tid & 3) * 16;
    float acc[16];
#pragma unroll
    for (int j = 0; j < 16; j++) acc[j] = 0.f;
    float dv = 0.f;
#pragma unroll
    for (int d = 0; d < 64; d++) {
        float qv = qs[r][d];
        dv += qv * kss[d];
#pragma unroll
        for (int j = 0; j < 16; j++) acc[j] += qv * cs[d][e0 + j];
    }
    float Dinv = 1.f / dv;
    size_t base = (size_t)(rowbase + r) * 512 + h * 64 + e0;
#pragma unroll
    for (int j = 0; j < 16; j++) {
        float val = acc[j] * Dinv + qs[r][e0 + j];
        __nv_bfloat16 hh = __float2bfloat16(val);
        Oh[base + j] = hh;
        Ol[base + j] = __float2bfloat16(val - __bfloat162float(hh));
    }
}

// ---------------------------------------------------------------------------
extern "C" void kernel_launch(void* const* d_in, const int* in_sizes, int n_in,
                              void* d_out, int out_size)
{
    const float* x  = (const float*)d_in[0];
    const float* Wq = (const float*)d_in[1];
    const float* bq = (const float*)d_in[2];
    const float* Wk = (const float*)d_in[3];
    const float* bk = (const float*)d_in[4];
    const float* Wv = (const float*)d_in[5];
    const float* bv = (const float*)d_in[6];
    const float* Wp = (const float*)d_in[7];
    const float* bp = (const float*)d_in[8];
    float* out = (float*)d_out;

    float *q, *k, *v, *ctx, *ksum, *ctxp, *ksump;
    __nv_bfloat16 *xh, *xl, *oh, *ol, *wh, *wl;
    cudaGetSymbolAddress((void**)&q, g_q);
    cudaGetSymbolAddress((void**)&k, g_k);
    cudaGetSymbolAddress((void**)&v, g_v);
    cudaGetSymbolAddress((void**)&ctx, g_ctx);
    cudaGetSymbolAddress((void**)&ksum, g_ksum);
    cudaGetSymbolAddress((void**)&ctxp, g_ctxp);
    cudaGetSymbolAddress((void**)&ksump, g_ksump);
    cudaGetSymbolAddress((void**)&xh, g_xh);
    cudaGetSymbolAddress((void**)&xl, g_xl);
    cudaGetSymbolAddress((void**)&oh, g_oh);
    cudaGetSymbolAddress((void**)&ol, g_ol);
    cudaGetSymbolAddress((void**)&wh, g_wh);
    cudaGetSymbolAddress((void**)&wl, g_wl);

    cudaFuncSetAttribute(mma_gemm_k<true>, cudaFuncAttributeMaxDynamicSharedMemorySize,
                         SMEM_GEMM);
    cudaFuncSetAttribute(mma_gemm_k<false>, cudaFuncAttributeMaxDynamicSharedMemorySize,
                         SMEM_GEMM);

    // one fused hi/lo split for x + all weights
    split_all_k<<<(NX + 4 * NW1) / 4 / 256, 256>>>(x, Wq, Wk, Wv, Wp, xh, xl, wh, wl);

    // fused QKV GEMM + softmax epilogue (q,k) / bias (v)
    GArgs aqkv{xh, xl, wh, wl, bq, bk, bv, q, k, v};
    mma_gemm_k<true><<<dim3(12, 128), 256, SMEM_GEMM>>>(aqkv);

    ctx_partial_k<<<dim3(NBH, TSPLIT), 256>>>(k, v, ctxp, ksump);
    reduce_all_k<<<(NBH * 4096 + NBH * 64 + 255) / 256, 256>>>(ctxp, ksump, ctx, ksum);

    attn_out_k<<<dim3(NBH, 64), 256>>>(q, ctx, ksum, oh, ol);

    // output projection (plain)
    GArgs ap{oh, ol, wh + 3 * NW1, wl + 3 * NW1, bp, bp, bp, out, out, out};
    mma_gemm_k<false><<<dim3(4, 128), 256, SMEM_GEMM>>>(ap);
}

// round 6
// speedup vs baseline: 1.7064x; 1.7064x over previous
#include <cuda_runtime.h>
#include <cuda_fp16.h>
#include <cstdint>

// Problem constants
#define M_TOT 16384          // B*T
#define NDIM  512
#define NBH   32             // B*H
#define TSPLIT 32
#define NX  (M_TOT * NDIM)   // 8388608
#define NW1 (NDIM * NDIM)    // 262144

// ---------------- scratch (__device__ globals; no allocation allowed) -------
__device__ float  g_q[M_TOT * NDIM];            // q post-softmax, fp32
__device__ __half g_kh[M_TOT * NDIM];           // k post-softmax, fp16
__device__ __half g_vh[M_TOT * NDIM];           // v, fp16
__device__ __half g_oh[M_TOT * NDIM];           // attn out, fp16
__device__ float  g_ctx[NBH * 64 * 64];
__device__ float  g_ksum[NBH * 64];
__device__ float  g_ctxp[TSPLIT * NBH * 64 * 64];
__device__ float  g_ksump[TSPLIT * NBH * 64];
__device__ __half g_xf[NX];                     // x fp16
__device__ __half g_wf[4 * NW1];                // Wq|Wk|Wv|Wp fp16

// ---------------- helpers ---------------------------------------------------
__device__ __forceinline__ uint32_t smem_u32(const void* p) {
    uint32_t a;
    asm("{ .reg .u64 t; cvta.to.shared.u64 t, %1; cvt.u32.u64 %0, t; }" : "=r"(a) : "l"(p));
    return a;
}
#define SWZ(o) ((o) ^ (((o) >> 3) & 0x70))

__device__ __forceinline__ void cp16(uint32_t dst, const void* src) {
    asm volatile("cp.async.cg.shared.global [%0], [%1], 16;" :: "r"(dst), "l"(src));
}
#define CP_COMMIT() asm volatile("cp.async.commit_group;" ::: "memory")
#define CP_WAIT(n)  asm volatile("cp.async.wait_group %0;" :: "n"(n) : "memory")

#define LDSM4(r, addr) \
    asm volatile("ldmatrix.sync.aligned.m8n8.x4.shared.b16 {%0,%1,%2,%3}, [%4];" \
        : "=r"((r)[0]), "=r"((r)[1]), "=r"((r)[2]), "=r"((r)[3]) : "r"(addr))

#define MMA_F16(d, a, b0, b1) \
    asm volatile("mma.sync.aligned.m16n8k16.row.col.f32.f16.f16.f32 " \
        "{%0,%1,%2,%3}, {%4,%5,%6,%7}, {%8,%9}, {%0,%1,%2,%3};" \
        : "+f"((d)[0]), "+f"((d)[1]), "+f"((d)[2]), "+f"((d)[3]) \
        : "r"((a)[0]), "r"((a)[1]), "r"((a)[2]), "r"((a)[3]), "r"(b0), "r"(b1))

// ---------------------------------------------------------------------------
// HMMA fp16 GEMM: C[M,N] = A[M,512] * W[N,512]^T + bias, optional fused
// per-head softmax. Tile BM=128, BN=128, BK=64; 8 warps (4m x 2n), warp 32x64.
// 3-stage cp.async pipeline (32KB/stage), occupancy 2.
// MODE 0: fused QKV (grid.x=12; slice0 -> q fp32 + softmax, slice1 -> k fp16 +
//         softmax, slice2 -> v fp16 + bias). MODE 1: plain fp32 out (grid.x=4).
// ---------------------------------------------------------------------------
#define BKB   128            // bytes per smem row (64 fp16)
#define K0B   16384          // one 128x64 fp16 tile
#define STG   (2 * K0B)      // 32KB stage: A | B
#define NSTG  3
#define SMEM_GEMM (NSTG * STG)
#define K0STEPS 8

struct GArgs {
    const __half *A, *W;                      // W: base of (multi-)slice weights
    const float *b0, *b1, *b2;                // bias per 512-col slice
    float* qf;                                // slice 0 out (fp32) / plain out
    __half *kh, *vh;                          // slice 1,2 out (fp16)
};

__device__ __forceinline__ void load_k0(
    uint32_t sbase, int stage, int k0, int bm, int bnn, int tid,
    const __half* A, const __half* B)
{
    uint32_t s = sbase + stage * STG;
#pragma unroll
    for (int t = 0; t < 4; t++) {
        int idx = tid + t * 256;                  // 1024 x 16B per tile
        int row = idx >> 3, c = idx & 7;
        uint32_t off = SWZ((uint32_t)(row * BKB + c * 16));
        cp16(s + off,       A + (size_t)(bm + row) * 512 + k0 + c * 8);
        cp16(s + K0B + off, B + (size_t)(bnn + row) * 512 + k0 + c * 8);
    }
}

template <int MODE>
__global__ __launch_bounds__(256, 2) void mma_gemm_k(GArgs args)
{
    extern __shared__ char smem[];
    uint32_t sbase = smem_u32(smem);

    const int tid = threadIdx.x;
    const int lane = tid & 31;
    const int wid = tid >> 5;
    const int wm = (wid & 3) * 32;
    const int wn = (wid >> 2) * 64;
    const int bm = blockIdx.y * 128;
    const int bn = blockIdx.x * 128;
    const int slice = bn >> 9;
    const int bnn = bn & 511;

    const __half* W = args.W + (size_t)slice * NW1;
    const float* bias = (slice == 0) ? args.b0 : (slice == 1) ? args.b1 : args.b2;
    const bool do_sm = (MODE == 0) && (slice < 2);

    float acc[2][8][4];
#pragma unroll
    for (int i = 0; i < 2; i++)
#pragma unroll
        for (int j = 0; j < 8; j++)
#pragma unroll
            for (int p = 0; p < 4; p++) acc[i][j][p] = 0.f;

    const int a_row = wm + (lane & 15);
    const int a_cb  = (lane >> 4) * 16;
    const int b_row = wn + (lane & 7) + ((lane >> 4) & 1) * 8;
    const int b_cb  = ((lane >> 3) & 1) * 16;

    load_k0(sbase, 0, 0, bm, bnn, tid, args.A, W);
    CP_COMMIT();
    load_k0(sbase, 1, 64, bm, bnn, tid, args.A, W);
    CP_COMMIT();

    for (int i = 0; i < K0STEPS; i++) {
        CP_WAIT(1);
        __syncthreads();
        if (i + 2 < K0STEPS)
            load_k0(sbase, (i + 2) % NSTG, (i + 2) * 64, bm, bnn, tid, args.A, W);
        CP_COMMIT();

        uint32_t sA = sbase + (i % NSTG) * STG;
        uint32_t sB = sA + K0B;
#pragma unroll
        for (int ks = 0; ks < 4; ks++) {
            uint32_t a[2][4], b[4][4];
#pragma unroll
            for (int mi = 0; mi < 2; mi++)
                LDSM4(a[mi], sA + SWZ((uint32_t)((a_row + mi * 16) * BKB + ks * 32 + a_cb)));
#pragma unroll
            for (int nb = 0; nb < 4; nb++)
                LDSM4(b[nb], sB + SWZ((uint32_t)((b_row + nb * 16) * BKB + ks * 32 + b_cb)));
#pragma unroll
            for (int mi = 0; mi < 2; mi++)
#pragma unroll
                for (int nb = 0; nb < 4; nb++) {
                    MMA_F16(acc[mi][nb * 2 + 0], a[mi], b[nb][0], b[nb][1]);
                    MMA_F16(acc[mi][nb * 2 + 1], a[mi], b[nb][2], b[nb][3]);
                }
        }
    }

    // ---- epilogue: bias, optional softmax, store --------------------------
#pragma unroll
    for (int nf = 0; nf < 8; nf++) {
        int col = bnn + wn + (lane & 3) * 2 + nf * 8;
        float bb0 = __ldg(bias + col);
        float bb1 = __ldg(bias + col + 1);
#pragma unroll
        for (int mi = 0; mi < 2; mi++) {
            acc[mi][nf][0] += bb0; acc[mi][nf][1] += bb1;
            acc[mi][nf][2] += bb0; acc[mi][nf][3] += bb1;
        }
    }

    if (do_sm) {
        // per-row softmax over the warp's 64 cols (row = lane quad)
#pragma unroll
        for (int mi = 0; mi < 2; mi++)
#pragma unroll
            for (int half = 0; half < 2; half++) {
                float m = -1e30f;
#pragma unroll
                for (int nf = 0; nf < 8; nf++)
                    m = fmaxf(m, fmaxf(acc[mi][nf][half * 2], acc[mi][nf][half * 2 + 1]));
                m = fmaxf(m, __shfl_xor_sync(0xffffffffu, m, 1));
                m = fmaxf(m, __shfl_xor_sync(0xffffffffu, m, 2));
                float s = 0.f;
#pragma unroll
                for (int nf = 0; nf < 8; nf++) {
                    float e0 = __expf(acc[mi][nf][half * 2] - m);
                    float e1 = __expf(acc[mi][nf][half * 2 + 1] - m);
                    acc[mi][nf][half * 2] = e0;
                    acc[mi][nf][half * 2 + 1] = e1;
                    s += e0 + e1;
                }
                s += __shfl_xor_sync(0xffffffffu, s, 1);
                s += __shfl_xor_sync(0xffffffffu, s, 2);
                float inv = 1.f / s;
#pragma unroll
                for (int nf = 0; nf < 8; nf++) {
                    acc[mi][nf][half * 2] *= inv;
                    acc[mi][nf][half * 2 + 1] *= inv;
                }
            }
    }

    const int r0 = bm + wm + (lane >> 2);
    const int c0 = bnn + wn + (lane & 3) * 2;

    if (MODE == 1 || slice == 0) {
        float* out = args.qf;
#pragma unroll
        for (int nf = 0; nf < 8; nf++) {
            int col = c0 + nf * 8;
#pragma unroll
            for (int mi = 0; mi < 2; mi++) {
                int row = r0 + mi * 16;
                float2 v0 = {acc[mi][nf][0], acc[mi][nf][1]};
                float2 v1 = {acc[mi][nf][2], acc[mi][nf][3]};
                *(float2*)(out + (size_t)row * 512 + col) = v0;
                *(float2*)(out + (size_t)(row + 8) * 512 + col) = v1;
            }
        }
    } else {
        __half* out = (slice == 1) ? args.kh : args.vh;
#pragma unroll
        for (int nf = 0; nf < 8; nf++) {
            int col = c0 + nf * 8;
#pragma unroll
            for (int mi = 0; mi < 2; mi++) {
                int row = r0 + mi * 16;
                __half2 v0 = __floats2half2_rn(acc[mi][nf][0], acc[mi][nf][1]);
                __half2 v1 = __floats2half2_rn(acc[mi][nf][2], acc[mi][nf][3]);
                *(__half2*)(out + (size_t)row * 512 + col) = v0;
                *(__half2*)(out + (size_t)(row + 8) * 512 + col) = v1;
            }
        }
    }
}

// ---------------------------------------------------------------------------
// fused fp32 -> fp16 conversion: x + all four weights
// ---------------------------------------------------------------------------
__global__ __launch_bounds__(256) void conv_all_k(
    const float* __restrict__ x,
    const float* __restrict__ Wq, const float* __restrict__ Wk,
    const float* __restrict__ Wv, const float* __restrict__ Wp,
    __half* __restrict__ xf, __half* __restrict__ wf)
{
    int i = (blockIdx.x * 256 + threadIdx.x) * 4;
    const float* src;
    __half* dst;
    int o;
    if (i < NX) { src = x; dst = xf; o = i; }
    else {
        int j = i - NX;
        int w = j >> 18;                  // NW1 = 2^18
        o = j & (NW1 - 1);
        src = (w == 0) ? Wq : (w == 1) ? Wk : (w == 2) ? Wv : Wp;
        dst = wf + ((size_t)w << 18);
    }
    float4 v = *(const float4*)(src + o);
    *(__half2*)(dst + o)     = __floats2half2_rn(v.x, v.y);
    *(__half2*)(dst + o + 2) = __floats2half2_rn(v.z, v.w);
}

// ---------------------------------------------------------------------------
// context partials + k_sum partials; k,v read as fp16
// ---------------------------------------------------------------------------
__global__ __launch_bounds__(256) void ctx_partial_k(
    const __half* __restrict__ K, const __half* __restrict__ V,
    float* __restrict__ ctxp, float* __restrict__ ksump)
{
    __shared__ float ks[32][65];
    __shared__ float vs[32][65];
    const int bh = blockIdx.x, b = bh >> 3, h = bh & 7;
    const int ts = blockIdx.y, tid = threadIdx.x;
    const int tx = tid & 15, ty = tid >> 4;
    const int col = tid & 63, trow = tid >> 6;

    float acc[4][4];
#pragma unroll
    for (int i = 0; i < 4; i++)
#pragma unroll
        for (int j = 0; j < 4; j++) acc[i][j] = 0.f;
    float ksacc[4] = {0.f, 0.f, 0.f, 0.f};
    const int rowbase = b * 4096 + ts * 128;

    for (int tt = 0; tt < 128; tt += 32) {
#pragma unroll
        for (int p = 0; p < 8; p++) {
            int t = trow + p * 4;
            size_t g = (size_t)(rowbase + tt + t) * 512 + h * 64 + col;
            ks[t][col] = __half2float(K[g]);
            vs[t][col] = __half2float(V[g]);
        }
        __syncthreads();
#pragma unroll
        for (int t = 0; t < 32; t++) {
            float a[4], bb[4];
#pragma unroll
            for (int i = 0; i < 4; i++) a[i] = ks[t][ty * 4 + i];
#pragma unroll
            for (int j = 0; j < 4; j++) bb[j] = vs[t][tx * 4 + j];
#pragma unroll
            for (int i = 0; i < 4; i++)
#pragma unroll
                for (int j = 0; j < 4; j++) acc[i][j] += a[i] * bb[j];
            if (tx == 0)
#pragma unroll
                for (int i = 0; i < 4; i++) ksacc[i] += a[i];
        }
        __syncthreads();
    }
    float* cp = ctxp + (size_t)(ts * NBH + bh) * 4096;
#pragma unroll
    for (int i = 0; i < 4; i++)
#pragma unroll
        for (int j = 0; j < 4; j++)
            cp[(ty * 4 + i) * 64 + tx * 4 + j] = acc[i][j];
    if (tx == 0)
#pragma unroll
        for (int i = 0; i < 4; i++)
            ksump[(size_t)(ts * NBH + bh) * 64 + ty * 4 + i] = ksacc[i];
}

// combined reduce: ctx (NBH*4096) then ksum (NBH*64)
__global__ void reduce_all_k(const float* __restrict__ ctxp,
                             const float* __restrict__ ksump,
                             float* __restrict__ ctx, float* __restrict__ ksum)
{
    int i = blockIdx.x * blockDim.x + threadIdx.x;
    if (i < NBH * 4096) {
        float s = 0.f;
#pragma unroll
        for (int p = 0; p < TSPLIT; p++) s += ctxp[(size_t)p * NBH * 4096 + i];
        ctx[i] = s;
    } else {
        int j = i - NBH * 4096;
        if (j < NBH * 64) {
            float s = 0.f;
#pragma unroll
            for (int p = 0; p < TSPLIT; p++) s += ksump[(size_t)p * NBH * 64 + j];
            ksum[j] = s;
        }
    }
}

// ---------------------------------------------------------------------------
// out = (q @ ctx) * Dinv + q  -> fp16 o for final GEMM. q read fp32.
// ---------------------------------------------------------------------------
__global__ __launch_bounds__(256) void attn_out_k(
    const float* __restrict__ Q, const float* __restrict__ ctx,
    const float* __restrict__ ksum, __half* __restrict__ Oh)
{
    __shared__ float cs[64][64];
    __shared__ float qs[64][65];
    __shared__ float kss[64];
    const int bh = blockIdx.x, b = bh >> 3, h = bh & 7;
    const int tb = blockIdx.y, tid = threadIdx.x;

    const float* cg = ctx + (size_t)bh * 4096;
    for (int i = tid; i < 4096; i += 256) cs[i >> 6][i & 63] = cg[i];
    if (tid < 64) kss[tid] = ksum[bh * 64 + tid];

    const int rowbase = b * 4096 + tb * 64;
    const int col = tid & 63, rr = tid >> 6;
#pragma unroll
    for (int p = 0; p < 16; p++) {
        int r = rr + p * 4;
        qs[r][col] = Q[(size_t)(rowbase + r) * 512 + h * 64 + col];
    }
    __syncthreads();

    const int r = tid >> 2, e0 = (tid & 3) * 16;
    float acc[16];
#pragma unroll
    for (int j = 0; j < 16; j++) acc[j] = 0.f;
    float dv = 0.f;
#pragma unroll
    for (int d = 0; d < 64; d++) {
        float qv = qs[r][d];
        dv += qv * kss[d];
#pragma unroll
        for (int j = 0; j < 16; j++) acc[j] += qv * cs[d][e0 + j];
    }
    float Dinv = 1.f / dv;
    size_t base = (size_t)(rowbase + r) * 512 + h * 64 + e0;
#pragma unroll
    for (int j = 0; j < 16; j += 2) {
        float v0 = acc[j] * Dinv + qs[r][e0 + j];
        float v1 = acc[j + 1] * Dinv + qs[r][e0 + j + 1];
        *(__half2*)(Oh + base + j) = __floats2half2_rn(v0, v1);
    }
}

// ---------------------------------------------------------------------------
extern "C" void kernel_launch(void* const* d_in, const int* in_sizes, int n_in,
                              void* d_out, int out_size)
{
    const float* x  = (const float*)d_in[0];
    const float* Wq = (const float*)d_in[1];
    const float* bq = (const float*)d_in[2];
    const float* Wk = (const float*)d_in[3];
    const float* bk = (const float*)d_in[4];
    const float* Wv = (const float*)d_in[5];
    const float* bv = (const float*)d_in[6];
    const float* Wp = (const float*)d_in[7];
    const float* bp = (const float*)d_in[8];
    float* out = (float*)d_out;

    float *q, *ctx, *ksum, *ctxp, *ksump;
    __half *kh, *vh, *oh, *xf, *wf;
    cudaGetSymbolAddress((void**)&q, g_q);
    cudaGetSymbolAddress((void**)&kh, g_kh);
    cudaGetSymbolAddress((void**)&vh, g_vh);
    cudaGetSymbolAddress((void**)&oh, g_oh);
    cudaGetSymbolAddress((void**)&ctx, g_ctx);
    cudaGetSymbolAddress((void**)&ksum, g_ksum);
    cudaGetSymbolAddress((void**)&ctxp, g_ctxp);
    cudaGetSymbolAddress((void**)&ksump, g_ksump);
    cudaGetSymbolAddress((void**)&xf, g_xf);
    cudaGetSymbolAddress((void**)&wf, g_wf);

    cudaFuncSetAttribute(mma_gemm_k<0>, cudaFuncAttributeMaxDynamicSharedMemorySize,
                         SMEM_GEMM);
    cudaFuncSetAttribute(mma_gemm_k<1>, cudaFuncAttributeMaxDynamicSharedMemorySize,
                         SMEM_GEMM);

    // fp32 -> fp16 conversions (x + all weights, one launch)
    conv_all_k<<<(NX + 4 * NW1) / 4 / 256, 256>>>(x, Wq, Wk, Wv, Wp, xf, wf);

    // fused QKV GEMM + softmax epilogue
    GArgs aqkv{xf, wf, bq, bk, bv, q, kh, vh};
    mma_gemm_k<0><<<dim3(12, 128), 256, SMEM_GEMM>>>(aqkv);

    ctx_partial_k<<<dim3(NBH, TSPLIT), 256>>>(kh, vh, ctxp, ksump);
    reduce_all_k<<<(NBH * 4096 + NBH * 64 + 255) / 256, 256>>>(ctxp, ksump, ctx, ksum);

    attn_out_k<<<dim3(NBH, 64), 256>>>(q, ctx, ksum, oh);

    // output projection (plain fp32 out)
    GArgs ap{oh, wf + 3 * NW1, bp, bp, bp, out, nullptr, nullptr};
    mma_gemm_k<1><<<dim3(4, 128), 256, SMEM_GEMM>>>(ap);
}